// round 2
// baseline (speedup 1.0000x reference)
#include <cuda_runtime.h>
#include <cuda_bf16.h>
#include <cstdint>

// ---------------------------------------------------------------------------
// Problem constants
// ---------------------------------------------------------------------------
#define BATCH 128
#define TLEN  4096
#define HID   13
#define G4    52          // 4*HID
#define NSEQ  256         // BATCH * 2 directions

// ---------------------------------------------------------------------------
// Scratch (device globals — no allocation allowed)
// ---------------------------------------------------------------------------
__device__ float g_pre[(size_t)TLEN * NSEQ * G4];     // 218 MB: [t][seq][k][4gates]
__device__ float g_bufA[(size_t)BATCH * TLEN * 26];   // 54.5 MB layer ping
__device__ float g_bufB[(size_t)BATCH * TLEN * 26];   // 54.5 MB layer pong

// ---------------------------------------------------------------------------
// f32x2 packed math helpers (Blackwell FFMA2 path, PTX-only per SASS_QUICKREF)
// ---------------------------------------------------------------------------
__device__ __forceinline__ unsigned long long pk2(float x, float y) {
    unsigned long long r;
    asm("mov.b64 %0, {%1, %2};" : "=l"(r) : "f"(x), "f"(y));
    return r;
}
__device__ __forceinline__ float2 upk2(unsigned long long v) {
    float2 r;
    asm("mov.b64 {%0, %1}, %2;" : "=f"(r.x), "=f"(r.y) : "l"(v));
    return r;
}
__device__ __forceinline__ unsigned long long fma2(unsigned long long a,
                                                   unsigned long long b,
                                                   unsigned long long c) {
    unsigned long long d;
    asm("fma.rn.f32x2 %0, %1, %2, %3;" : "=l"(d) : "l"(a), "l"(b), "l"(c));
    return d;
}
__device__ __forceinline__ unsigned long long add2(unsigned long long a,
                                                   unsigned long long b) {
    unsigned long long d;
    asm("add.rn.f32x2 %0, %1, %2;" : "=l"(d) : "l"(a), "l"(b));
    return d;
}

// Activations
__device__ __forceinline__ float ex2a(float x) {
    float r; asm("ex2.approx.f32 %0, %1;" : "=f"(r) : "f"(x)); return r;
}
__device__ __forceinline__ float rcpa(float x) {
    float r; asm("rcp.approx.f32 %0, %1;" : "=f"(r) : "f"(x)); return r;
}
__device__ __forceinline__ float tanha(float x) {
    float r; asm("tanh.approx.f32 %0, %1;" : "=f"(r) : "f"(x)); return r;
}
// sigmoid via MUFU.TANH: sigma(x) = 0.5*tanh(0.5x) + 0.5
__device__ __forceinline__ float sigm_fast(float x) {
    return fmaf(0.5f, tanha(0.5f * x), 0.5f);
}

// ---------------------------------------------------------------------------
// Pre kernel: pre[t][seq][k][4] = x[b,t,:] @ W_ih[dir]^T + b_ih + b_hh
// One thread per (seq, t) row (52 outputs). Weights staged in shared as
// f32x2 gate pairs: m = k + 13*s, s=0 -> (i_k, f_k), s=1 -> (g_k, o_k).
// ---------------------------------------------------------------------------
template<int D>
__global__ void __launch_bounds__(128)
pre_kernel(const float* __restrict__ x,      // [BATCH][TLEN][D]
           const float* __restrict__ w_ih,   // [2][52][D]
           const float* __restrict__ b_ih,   // [2][52]
           const float* __restrict__ b_hh,   // [2][52]
           float* __restrict__ pre)          // [TLEN][NSEQ][52]
{
    __shared__ alignas(16) unsigned long long wp[D * 26];
    __shared__ unsigned long long bp[26];

    const int tid = threadIdx.x;
    const int gid = blockIdx.x * 128 + tid;          // < 2^20
    const int t   = gid & (TLEN - 1);
    const int seq = gid >> 12;                       // block-uniform (128 | 4096)
    const int dir = seq >> 7;
    const int b   = seq & 127;

    const float* W = w_ih + dir * G4 * D;

    for (int idx = tid; idx < D * 26; idx += 128) {
        const int d = idx / 26, m = idx % 26;
        const int k = m % 13, s = m / 13;
        const int j0 = s ? 26 + k : k;
        wp[idx] = pk2(W[j0 * D + d], W[(j0 + 13) * D + d]);
    }
    if (tid < 26) {
        const int k = tid % 13, s = tid / 13;
        const int j0 = s ? 26 + k : k;
        const float* bi = b_ih + dir * G4;
        const float* bh = b_hh + dir * G4;
        bp[tid] = pk2(bi[j0] + bh[j0], bi[j0 + 13] + bh[j0 + 13]);
    }
    __syncthreads();

    // Load x row into registers
    float xr[D];
    const float* xrow = x + ((size_t)b * TLEN + t) * D;
    if (D == 26) {
        const float2* g = (const float2*)xrow;       // 104B rows -> 8B aligned
        float2* xr2 = (float2*)xr;
#pragma unroll
        for (int i = 0; i < 13; i++) xr2[i] = g[i];
    } else {
#pragma unroll
        for (int d = 0; d < D; d++) xr[d] = xrow[d];
    }

    unsigned long long acc[26];
#pragma unroll
    for (int m = 0; m < 26; m++) acc[m] = bp[m];

#pragma unroll
    for (int d = 0; d < D; d++) {
        const unsigned long long x2 = pk2(xr[d], xr[d]);
        const ulonglong2* row = (const ulonglong2*)(wp + d * 26);
#pragma unroll
        for (int mm = 0; mm < 13; mm++) {
            const ulonglong2 w2 = row[mm];           // broadcast LDS.128
            acc[2 * mm]     = fma2(w2.x, x2, acc[2 * mm]);
            acc[2 * mm + 1] = fma2(w2.y, x2, acc[2 * mm + 1]);
        }
    }

    float4* outp = (float4*)(pre + ((size_t)t * NSEQ + seq) * G4);
#pragma unroll
    for (int k = 0; k < 13; k++) {
        const float2 p01 = upk2(acc[k]);         // (i, f)
        const float2 p23 = upk2(acc[13 + k]);    // (g, o)
        outp[k] = make_float4(p01.x, p01.y, p23.x, p23.y);
    }
}

// ---------------------------------------------------------------------------
// Recurrence kernel: one warp per batch. Lanes 0-12 = fwd dir, lanes 16-28 =
// bwd dir; lane k owns hidden element k (all 4 gates, two f32x2 chains).
// h broadcast via width-16 shuffles. Gate activations via MUFU.TANH
// (sigma(x)=0.5*tanh(x/2)+0.5); output tanh(c) kept exact via ex2/rcp on a
// pre-scaled cell cs = 2*log2(e)*c, fused as h = fma(-2o, rcp(1+2^cs), o).
// Pre tiles prefetched 8 steps deep.
// ---------------------------------------------------------------------------
__global__ void __launch_bounds__(32)
lstm_rec_kernel(const float* __restrict__ pre,   // [TLEN][NSEQ][52]
                const float* __restrict__ w_hh,  // [2][52][13]
                float* __restrict__ out)         // [BATCH][TLEN][26]
{
    const int lane = threadIdx.x;
    const int b    = blockIdx.x;
    const int dir  = lane >> 4;
    const int k    = lane & 15;
    const int kc   = (k < 13) ? k : 12;
    const bool act = (k < 13);

    // Pack recurrent weights: wA[kk] = (W[i_row][kk], W[f_row][kk]),
    //                         wB[kk] = (W[g_row][kk], W[o_row][kk])
    const float* W = w_hh + dir * G4 * HID;
    unsigned long long wA[13], wB[13];
#pragma unroll
    for (int kk = 0; kk < 13; kk++) {
        wA[kk] = pk2(W[kc * HID + kk],        W[(13 + kc) * HID + kk]);
        wB[kk] = pk2(W[(26 + kc) * HID + kk], W[(39 + kc) * HID + kk]);
    }

    const int seq = dir * BATCH + b;

    // pre pointer in float4 units: index = (t*NSEQ + seq)*13 + kc
    const long long stride4 = (dir == 0) ? (long long)(NSEQ * 13)
                                         : -(long long)(NSEQ * 13);
    const float4* pp = (const float4*)pre +
        (((size_t)(dir == 0 ? 0 : TLEN - 1) * NSEQ + seq) * 13 + kc);

    // output pointer: out[(b*TLEN + tt)*26 + dir*13 + k]
    const long long ostride = (dir == 0) ? 26 : -26;
    float* op = out + ((size_t)b * TLEN + (dir == 0 ? 0 : TLEN - 1)) * 26
                    + dir * 13 + k;

    // 8-deep prefetch ring
    float4 buf[8];
#pragma unroll
    for (int j = 0; j < 8; j++) buf[j] = pp[(long long)j * stride4];
    pp += 8 * stride4;

    float h  = 0.0f;
    float cs = 0.0f;   // pre-scaled cell: cs = 2*log2(e) * c
    const float KSC = 2.8853900817779268f;   // 2*log2(e)

    for (int i = 0; i < TLEN; i += 8) {
        const bool pf = (i < TLEN - 8);
#pragma unroll
        for (int j = 0; j < 8; j++) {
            const float4 p = buf[j];
            if (pf) buf[j] = pp[(long long)j * stride4];

            // gates: two packed accumulators, each split into 2 partial chains
            unsigned long long a0 = pk2(p.x, p.y);   // (i, f)
            unsigned long long a1 = pk2(p.z, p.w);   // (g, o)
            unsigned long long c0 = 0ull, c1 = 0ull;
#pragma unroll
            for (int kk = 0; kk < 13; kk++) {
                const float hv = __shfl_sync(0xffffffffu, h, kk, 16);
                const unsigned long long h2 = pk2(hv, hv);
                if (kk & 1) { c0 = fma2(wA[kk], h2, c0); c1 = fma2(wB[kk], h2, c1); }
                else        { a0 = fma2(wA[kk], h2, a0); a1 = fma2(wB[kk], h2, a1); }
            }
            a0 = add2(a0, c0);
            a1 = add2(a1, c1);

            const float2 g01 = upk2(a0);
            const float2 g23 = upk2(a1);
            const float si = sigm_fast(g01.x);
            const float sf = sigm_fast(g01.y);
            const float tg = tanha(g23.x);
            const float so = sigm_fast(g23.y);

            // cs = sf*cs + 2log2e * (si*tg)
            cs = fmaf(sf, cs, KSC * (si * tg));
            // h = so * tanh(c) = so * (1 - 2/(1+2^cs)) = fma(-2so, r, so)
            const float r  = rcpa(1.0f + ex2a(cs));
            const float o2 = so + so;
            h = fmaf(-o2, r, so);

            if (act) *op = h;
            op += ostride;
        }
        pp += 8 * stride4;
    }
}

// ---------------------------------------------------------------------------
// Launch: 4 layers x (pre GEMM -> recurrence). Layer 0 D=13, layers 1-3 D=26.
// ---------------------------------------------------------------------------
extern "C" void kernel_launch(void* const* d_in, const int* in_sizes, int n_in,
                              void* d_out, int out_size)
{
    const float* x      = (const float*)d_in[0];
    const float* w_ih0  = (const float*)d_in[1];
    const float* w_hh0  = (const float*)d_in[2];
    const float* b_ih0  = (const float*)d_in[3];
    const float* b_hh0  = (const float*)d_in[4];
    const float* w_ihr  = (const float*)d_in[5];  // [3][2][52][26]
    const float* w_hhr  = (const float*)d_in[6];  // [3][2][52][13]
    const float* b_ihr  = (const float*)d_in[7];  // [3][2][52]
    const float* b_hhr  = (const float*)d_in[8];  // [3][2][52]
    float* out = (float*)d_out;

    float *pre, *bufA, *bufB;
    cudaGetSymbolAddress((void**)&pre,  g_pre);
    cudaGetSymbolAddress((void**)&bufA, g_bufA);
    cudaGetSymbolAddress((void**)&bufB, g_bufB);

    const int PRE_BLOCKS = (NSEQ * TLEN) / 128;   // 8192

    // Layer 0 (D = 13)
    pre_kernel<13><<<PRE_BLOCKS, 128>>>(x, w_ih0, b_ih0, b_hh0, pre);
    lstm_rec_kernel<<<BATCH, 32>>>(pre, w_hh0, bufA);

    // Layers 1-3 (D = 26)
    const float* ins[3]  = {bufA, bufB, bufA};
    float*       outs[3] = {bufB, bufA, out};
    for (int l = 0; l < 3; l++) {
        pre_kernel<26><<<PRE_BLOCKS, 128>>>(ins[l],
                                            w_ihr + (size_t)l * 2 * G4 * 26,
                                            b_ihr + (size_t)l * 2 * G4,
                                            b_hhr + (size_t)l * 2 * G4,
                                            pre);
        lstm_rec_kernel<<<BATCH, 32>>>(pre,
                                       w_hhr + (size_t)l * 2 * G4 * HID,
                                       outs[l]);
    }
}

// round 3
// speedup vs baseline: 1.9344x; 1.9344x over previous
#include <cuda_runtime.h>
#include <cuda_bf16.h>
#include <cstdint>

// ---------------------------------------------------------------------------
// Problem constants
// ---------------------------------------------------------------------------
#define BATCH 128
#define TLEN  4096
#define HID   13
#define G4    52
#define NSEQ  256

// ---------------------------------------------------------------------------
// Scratch (device globals — no allocation allowed)
// ---------------------------------------------------------------------------
__device__ float g_pre[(size_t)NSEQ * TLEN * G4];        // [seq][t][52]  218 MB
__device__ float g_yA[(size_t)NSEQ * TLEN * HID];        // [seq][t][13]  54.5 MB
__device__ float g_yB[(size_t)NSEQ * TLEN * HID];        // ping-pong

typedef unsigned long long u64;

// ---------------------------------------------------------------------------
// f32x2 packed helpers
// ---------------------------------------------------------------------------
__device__ __forceinline__ u64 pk2(float x, float y) {
    u64 r; asm("mov.b64 %0, {%1, %2};" : "=l"(r) : "f"(x), "f"(y)); return r;
}
__device__ __forceinline__ float2 upk2(u64 v) {
    float2 r; asm("mov.b64 {%0, %1}, %2;" : "=f"(r.x), "=f"(r.y) : "l"(v)); return r;
}
__device__ __forceinline__ u64 fma2(u64 a, u64 b, u64 c) {
    u64 d; asm("fma.rn.f32x2 %0, %1, %2, %3;" : "=l"(d) : "l"(a), "l"(b), "l"(c)); return d;
}
__device__ __forceinline__ u64 add2(u64 a, u64 b) {
    u64 d; asm("add.rn.f32x2 %0, %1, %2;" : "=l"(d) : "l"(a), "l"(b)); return d;
}

// Activations
__device__ __forceinline__ float ex2a(float x) {
    float r; asm("ex2.approx.f32 %0, %1;" : "=f"(r) : "f"(x)); return r;
}
__device__ __forceinline__ float rcpa(float x) {
    float r; asm("rcp.approx.f32 %0, %1;" : "=f"(r) : "f"(x)); return r;
}
__device__ __forceinline__ float tanha(float x) {
    float r; asm("tanh.approx.f32 %0, %1;" : "=f"(r) : "f"(x)); return r;
}
__device__ __forceinline__ float sigm_fast(float x) {   // sigma(x)=0.5*tanh(x/2)+0.5
    return fmaf(0.5f, tanha(0.5f * x), 0.5f);
}

// cp.async helpers
__device__ __forceinline__ void cp16(unsigned sdst, const void* gsrc) {
    asm volatile("cp.async.cg.shared.global [%0], [%1], 16;"
                 :: "r"(sdst), "l"(gsrc) : "memory");
}
__device__ __forceinline__ void cp_commit() {
    asm volatile("cp.async.commit_group;" ::: "memory");
}
__device__ __forceinline__ void cp_wait8() {
    asm volatile("cp.async.wait_group 8;" ::: "memory");
}

// ---------------------------------------------------------------------------
// Pre kernel, layer 0 (D=13, reads external x [B][T][13]).
// Block = 128 threads = one (seq, 128-t tile). smem-staged in & out.
// Output layout: g_pre[seq][t][k][4gates] as float4 per k.
// ---------------------------------------------------------------------------
__global__ void __launch_bounds__(128)
pre0_kernel(const float* __restrict__ x,
            const float* __restrict__ w_ih,   // [2][52][13]
            const float* __restrict__ b_ih,   // [2][52]
            const float* __restrict__ b_hh,   // [2][52]
            float* __restrict__ pre)
{
    __shared__ alignas(16) u64 wp[13 * 26];
    __shared__ u64 bp[26];
    __shared__ alignas(16) float xs[128 * 13];
    __shared__ alignas(16) float ot[128 * 56];

    const int tid = threadIdx.x;
    const int seq = blockIdx.x >> 5;
    const int t0  = (blockIdx.x & 31) * 128;
    const int dir = seq >> 7;
    const int b   = seq & 127;

    const float* W = w_ih + dir * G4 * 13;
    for (int idx = tid; idx < 13 * 26; idx += 128) {
        const int d = idx / 26, m = idx % 26;
        const int k = m % 13, s = m / 13;
        const int j0 = s ? 26 + k : k;
        wp[idx] = pk2(W[j0 * 13 + d], W[(j0 + 13) * 13 + d]);
    }
    if (tid < 26) {
        const int k = tid % 13, s = tid / 13;
        const int j0 = s ? 26 + k : k;
        const float* bi = b_ih + dir * G4;
        const float* bh = b_hh + dir * G4;
        bp[tid] = pk2(bi[j0] + bh[j0], bi[j0 + 13] + bh[j0 + 13]);
    }
    // stage x rows (coalesced float4: region is 16B-aligned, 128*13 floats)
    {
        const float4* src = (const float4*)(x + ((size_t)b * TLEN + t0) * 13);
        float4* dst = (float4*)xs;
        for (int i = tid; i < 128 * 13 / 4; i += 128) dst[i] = src[i];
    }
    __syncthreads();

    u64 acc[26];
#pragma unroll
    for (int m = 0; m < 26; m++) acc[m] = bp[m];
#pragma unroll
    for (int d = 0; d < 13; d++) {
        const float xv = xs[tid * 13 + d];
        const u64 x2 = pk2(xv, xv);
        const ulonglong2* row = (const ulonglong2*)(wp + d * 26);
#pragma unroll
        for (int mm = 0; mm < 13; mm++) {
            const ulonglong2 w2 = row[mm];
            acc[2 * mm]     = fma2(w2.x, x2, acc[2 * mm]);
            acc[2 * mm + 1] = fma2(w2.y, x2, acc[2 * mm + 1]);
        }
    }
#pragma unroll
    for (int k = 0; k < 13; k++) {
        const float2 p01 = upk2(acc[k]);
        const float2 p23 = upk2(acc[13 + k]);
        *(float4*)(ot + tid * 56 + 4 * k) = make_float4(p01.x, p01.y, p23.x, p23.y);
    }
    __syncthreads();

    // coalesced store to g_pre (contiguous 128*52 floats)
    float4* preb = (float4*)(pre + ((size_t)seq * TLEN + t0) * G4);
    for (int j = tid; j < 128 * 13; j += 128) {
        const int r = j / 13, kk = j % 13;
        preb[j] = *(const float4*)(ot + r * 56 + kk * 4);
    }
}

// ---------------------------------------------------------------------------
// Pre kernel, layers 1-3 (D=26, reads compact y scratch [seq][t][13]).
// ---------------------------------------------------------------------------
__global__ void __launch_bounds__(128)
preR_kernel(const float* __restrict__ y,      // [NSEQ][TLEN][13]
            const float* __restrict__ w_ih,   // [2][52][26]
            const float* __restrict__ b_ih,
            const float* __restrict__ b_hh,
            float* __restrict__ pre)
{
    __shared__ alignas(16) u64 wp[26 * 26];
    __shared__ u64 bp[26];
    __shared__ alignas(16) float fb[128 * 13];
    __shared__ alignas(16) float bb[128 * 13];
    __shared__ alignas(16) float ot[128 * 56];

    const int tid = threadIdx.x;
    const int seq = blockIdx.x >> 5;
    const int t0  = (blockIdx.x & 31) * 128;
    const int dir = seq >> 7;
    const int b   = seq & 127;

    const float* W = w_ih + dir * G4 * 26;
    for (int idx = tid; idx < 26 * 26; idx += 128) {
        const int d = idx / 26, m = idx % 26;
        const int k = m % 13, s = m / 13;
        const int j0 = s ? 26 + k : k;
        wp[idx] = pk2(W[j0 * 26 + d], W[(j0 + 13) * 26 + d]);
    }
    if (tid < 26) {
        const int k = tid % 13, s = tid / 13;
        const int j0 = s ? 26 + k : k;
        const float* bi = b_ih + dir * G4;
        const float* bh = b_hh + dir * G4;
        bp[tid] = pk2(bi[j0] + bh[j0], bi[j0 + 13] + bh[j0 + 13]);
    }
    {
        const float4* sf = (const float4*)(y + ((size_t)b * TLEN + t0) * 13);
        const float4* sb = (const float4*)(y + ((size_t)(BATCH + b) * TLEN + t0) * 13);
        float4* df = (float4*)fb;
        float4* db = (float4*)bb;
        for (int i = tid; i < 128 * 13 / 4; i += 128) { df[i] = sf[i]; db[i] = sb[i]; }
    }
    __syncthreads();

    u64 acc[26];
#pragma unroll
    for (int m = 0; m < 26; m++) acc[m] = bp[m];
#pragma unroll
    for (int d = 0; d < 26; d++) {
        const float xv = (d < 13) ? fb[tid * 13 + d] : bb[tid * 13 + (d - 13)];
        const u64 x2 = pk2(xv, xv);
        const ulonglong2* row = (const ulonglong2*)(wp + d * 26);
#pragma unroll
        for (int mm = 0; mm < 13; mm++) {
            const ulonglong2 w2 = row[mm];
            acc[2 * mm]     = fma2(w2.x, x2, acc[2 * mm]);
            acc[2 * mm + 1] = fma2(w2.y, x2, acc[2 * mm + 1]);
        }
    }
#pragma unroll
    for (int k = 0; k < 13; k++) {
        const float2 p01 = upk2(acc[k]);
        const float2 p23 = upk2(acc[13 + k]);
        *(float4*)(ot + tid * 56 + 4 * k) = make_float4(p01.x, p01.y, p23.x, p23.y);
    }
    __syncthreads();

    float4* preb = (float4*)(pre + ((size_t)seq * TLEN + t0) * G4);
    for (int j = tid; j < 128 * 13; j += 128) {
        const int r = j / 13, kk = j % 13;
        preb[j] = *(const float4*)(ot + r * 56 + kk * 4);
    }
}

// ---------------------------------------------------------------------------
// Recurrence: one warp per batch; lanes 0-12 fwd, 16-28 bwd (lane k = hidden
// elem k). Gate inputs streamed via cp.async with explicit group pipelining
// (depth 8, 16-slot smem ring) — guaranteed latency hiding. h broadcast via
// width-16 shuffles. Writes compact y scratch [seq][t][13].
// ---------------------------------------------------------------------------
__global__ void __launch_bounds__(32)
lstm_rec_kernel(const float* __restrict__ pre,   // [NSEQ][TLEN][52]
                const float* __restrict__ w_hh,  // [2][52][13]
                float* __restrict__ yout)        // [NSEQ][TLEN][13]
{
    __shared__ alignas(16) float4 ring[16][32];

    const int lane = threadIdx.x;
    const int b    = blockIdx.x;
    const int dir  = lane >> 4;
    const int k    = lane & 15;
    const int kc   = (k < 13) ? k : 12;
    const bool act = (k < 13);

    const float* W = w_hh + dir * G4 * HID;
    u64 wA[13], wB[13];
#pragma unroll
    for (int kk = 0; kk < 13; kk++) {
        wA[kk] = pk2(W[kc * HID + kk],        W[(13 + kc) * HID + kk]);
        wB[kk] = pk2(W[(26 + kc) * HID + kk], W[(39 + kc) * HID + kk]);
    }

    const int seq = dir * BATCH + b;
    const int tstart = dir ? (TLEN - 1) : 0;
    const long long ss = (dir ? -1LL : 1LL) * (long long)(G4 * sizeof(float)); // per-step bytes

    const char* src0 = (const char*)(pre + ((size_t)seq * TLEN + tstart) * G4 + kc * 4);
    float* yp = yout + ((size_t)seq * TLEN + tstart) * HID + k;
    const long long ydel = (dir ? -1LL : 1LL) * HID;

    const unsigned sbase = (unsigned)__cvta_generic_to_shared(&ring[0][lane]);

    // prologue: steps 0..7 into slots 0..7, one group each
#pragma unroll
    for (int u = 0; u < 8; u++) {
        cp16(sbase + u * (unsigned)sizeof(float4) * 32, src0 + (long long)u * ss);
        cp_commit();
    }
    const char* psrc = src0 + 8 * ss;

    float h  = 0.0f;
    float cs = 0.0f;                               // 2*log2(e) * c
    const float KSC = 2.8853900817779268f;

    for (int blk = 0; blk < TLEN / 16; blk++) {
#pragma unroll
        for (int u = 0; u < 16; u++) {
            const int step = blk * 16 + u;
            if (step + 8 < TLEN)
                cp16(sbase + ((u + 8) & 15) * (unsigned)sizeof(float4) * 32, psrc);
            cp_commit();
            psrc += ss;
            cp_wait8();

            const float4 p = ring[u][lane];        // own 16B, ready per wait

            u64 a0 = 0ull, a1 = 0ull, c0 = 0ull, c1 = 0ull;
#pragma unroll
            for (int kk = 0; kk < 13; kk++) {
                const float hv = __shfl_sync(0xffffffffu, h, kk, 16);
                const u64 h2 = pk2(hv, hv);
                if (kk & 1) { c0 = fma2(wA[kk], h2, c0); c1 = fma2(wB[kk], h2, c1); }
                else        { a0 = fma2(wA[kk], h2, a0); a1 = fma2(wB[kk], h2, a1); }
            }
            a0 = add2(a0, add2(c0, pk2(p.x, p.y)));
            a1 = add2(a1, add2(c1, pk2(p.z, p.w)));

            const float2 g01 = upk2(a0);
            const float2 g23 = upk2(a1);
            const float si = sigm_fast(g01.x);
            const float sf = sigm_fast(g01.y);
            const float tg = tanha(g23.x);
            const float so = sigm_fast(g23.y);

            cs = fmaf(sf, cs, KSC * (si * tg));
            const float r  = rcpa(1.0f + ex2a(cs));
            h = fmaf(-(so + so), r, so);

            if (act) *yp = h;
            yp += ydel;
        }
    }
}

// ---------------------------------------------------------------------------
// Merge: y scratch [2][B][T][13] -> out [B][T][26]
// ---------------------------------------------------------------------------
__global__ void __launch_bounds__(128)
merge_kernel(const float* __restrict__ y, float* __restrict__ out)
{
    __shared__ alignas(16) float fb[128 * 13];
    __shared__ alignas(16) float bb[128 * 13];

    const int tid = threadIdx.x;
    const int b   = blockIdx.x >> 5;
    const int t0  = (blockIdx.x & 31) * 128;

    const float4* sf = (const float4*)(y + ((size_t)b * TLEN + t0) * 13);
    const float4* sb = (const float4*)(y + ((size_t)(BATCH + b) * TLEN + t0) * 13);
    float4* df = (float4*)fb;
    float4* db = (float4*)bb;
    for (int i = tid; i < 128 * 13 / 4; i += 128) { df[i] = sf[i]; db[i] = sb[i]; }
    __syncthreads();

    float4* ob = (float4*)(out + ((size_t)b * TLEN + t0) * 26);
    for (int j = tid; j < 128 * 26 / 4; j += 128) {
        float v[4];
#pragma unroll
        for (int e = 0; e < 4; e++) {
            const int f = j * 4 + e;
            const int t = f / 26, c = f % 26;
            v[e] = (c < 13) ? fb[t * 13 + c] : bb[t * 13 + (c - 13)];
        }
        ob[j] = make_float4(v[0], v[1], v[2], v[3]);
    }
}

// ---------------------------------------------------------------------------
// Launch
// ---------------------------------------------------------------------------
extern "C" void kernel_launch(void* const* d_in, const int* in_sizes, int n_in,
                              void* d_out, int out_size)
{
    const float* x      = (const float*)d_in[0];
    const float* w_ih0  = (const float*)d_in[1];
    const float* w_hh0  = (const float*)d_in[2];
    const float* b_ih0  = (const float*)d_in[3];
    const float* b_hh0  = (const float*)d_in[4];
    const float* w_ihr  = (const float*)d_in[5];
    const float* w_hhr  = (const float*)d_in[6];
    const float* b_ihr  = (const float*)d_in[7];
    const float* b_hhr  = (const float*)d_in[8];
    float* out = (float*)d_out;

    float *pre, *yA, *yB;
    cudaGetSymbolAddress((void**)&pre, g_pre);
    cudaGetSymbolAddress((void**)&yA,  g_yA);
    cudaGetSymbolAddress((void**)&yB,  g_yB);

    const int PRE_BLOCKS = NSEQ * (TLEN / 128);   // 8192

    // Layer 0
    pre0_kernel<<<PRE_BLOCKS, 128>>>(x, w_ih0, b_ih0, b_hh0, pre);
    lstm_rec_kernel<<<BATCH, 32>>>(pre, w_hh0, yA);

    // Layers 1-3
    const float* ins[3]  = {yA, yB, yA};
    float*       outs[3] = {yB, yA, yB};
    for (int l = 0; l < 3; l++) {
        preR_kernel<<<PRE_BLOCKS, 128>>>(ins[l],
                                         w_ihr + (size_t)l * 2 * G4 * 26,
                                         b_ihr + (size_t)l * 2 * G4,
                                         b_hhr + (size_t)l * 2 * G4,
                                         pre);
        lstm_rec_kernel<<<BATCH, 32>>>(pre,
                                       w_hhr + (size_t)l * 2 * G4 * HID,
                                       outs[l]);
    }

    // Final merge to [B][T][26]
    merge_kernel<<<BATCH * (TLEN / 128), 128>>>(yB, out);
}

// round 4
// speedup vs baseline: 2.3079x; 1.1931x over previous
#include <cuda_runtime.h>
#include <cuda_bf16.h>
#include <cstdint>

// ---------------------------------------------------------------------------
// Problem constants
// ---------------------------------------------------------------------------
#define BATCH 128
#define TLEN  4096
#define HID   13
#define G4    52
#define NSEQ  256

// ---------------------------------------------------------------------------
// Scratch (device globals — no allocation allowed)
// ---------------------------------------------------------------------------
// Gate scaling convention: i, f, o pre-activations (and their weights/biases)
// carry a factor 0.5 so sigma(x) = fma(0.5, tanh(acc), 0.5) with no pre-mul.
// g carries no scale (tanh applied directly).
__device__ float g_pre[(size_t)NSEQ * TLEN * G4];        // [seq][t][52]  218 MB
__device__ float g_yA[(size_t)NSEQ * TLEN * HID];        // [seq][t][13]  54.5 MB
__device__ float g_yB[(size_t)NSEQ * TLEN * HID];        // ping-pong

typedef unsigned long long u64;

// ---------------------------------------------------------------------------
// f32x2 packed helpers
// ---------------------------------------------------------------------------
__device__ __forceinline__ u64 pk2(float x, float y) {
    u64 r; asm("mov.b64 %0, {%1, %2};" : "=l"(r) : "f"(x), "f"(y)); return r;
}
__device__ __forceinline__ float2 upk2(u64 v) {
    float2 r; asm("mov.b64 {%0, %1}, %2;" : "=f"(r.x), "=f"(r.y) : "l"(v)); return r;
}
__device__ __forceinline__ u64 fma2(u64 a, u64 b, u64 c) {
    u64 d; asm("fma.rn.f32x2 %0, %1, %2, %3;" : "=l"(d) : "l"(a), "l"(b), "l"(c)); return d;
}
__device__ __forceinline__ u64 add2(u64 a, u64 b) {
    u64 d; asm("add.rn.f32x2 %0, %1, %2;" : "=l"(d) : "l"(a), "l"(b)); return d;
}

__device__ __forceinline__ float tanha(float x) {
    float r; asm("tanh.approx.f32 %0, %1;" : "=f"(r) : "f"(x)); return r;
}

// cp.async helpers
__device__ __forceinline__ void cp16(unsigned sdst, const void* gsrc) {
    asm volatile("cp.async.cg.shared.global [%0], [%1], 16;"
                 :: "r"(sdst), "l"(gsrc) : "memory");
}
__device__ __forceinline__ void cp_commit() {
    asm volatile("cp.async.commit_group;" ::: "memory");
}
__device__ __forceinline__ void cp_wait8() {
    asm volatile("cp.async.wait_group 8;" ::: "memory");
}

// ---------------------------------------------------------------------------
// Pre kernel, layer 0 (D=13, reads external x [B][T][13]).
// Output layout: g_pre[seq][t][k][4gates] float4 = (0.5*i, 0.5*f, g, 0.5*o).
// ---------------------------------------------------------------------------
__global__ void __launch_bounds__(128)
pre0_kernel(const float* __restrict__ x,
            const float* __restrict__ w_ih,   // [2][52][13]
            const float* __restrict__ b_ih,   // [2][52]
            const float* __restrict__ b_hh,   // [2][52]
            float* __restrict__ pre)
{
    __shared__ alignas(16) u64 wp[13 * 26];
    __shared__ u64 bp[26];
    __shared__ alignas(16) float xs[128 * 13];
    __shared__ alignas(16) float ot[128 * 56];

    const int tid = threadIdx.x;
    const int seq = blockIdx.x >> 5;
    const int t0  = (blockIdx.x & 31) * 128;
    const int dir = seq >> 7;
    const int b   = seq & 127;

    const float* W = w_ih + dir * G4 * 13;
    for (int idx = tid; idx < 13 * 26; idx += 128) {
        const int d = idx / 26, m = idx % 26;
        const int k = m % 13, s = m / 13;
        const int j0 = s ? 26 + k : k;
        const float s0 = s ? 1.0f : 0.5f;     // (i,f) scaled, g unscaled
        wp[idx] = pk2(s0 * W[j0 * 13 + d], 0.5f * W[(j0 + 13) * 13 + d]);
    }
    if (tid < 26) {
        const int k = tid % 13, s = tid / 13;
        const int j0 = s ? 26 + k : k;
        const float s0 = s ? 1.0f : 0.5f;
        const float* bi = b_ih + dir * G4;
        const float* bh = b_hh + dir * G4;
        bp[tid] = pk2(s0 * (bi[j0] + bh[j0]),
                      0.5f * (bi[j0 + 13] + bh[j0 + 13]));
    }
    {
        const float4* src = (const float4*)(x + ((size_t)b * TLEN + t0) * 13);
        float4* dst = (float4*)xs;
        for (int i = tid; i < 128 * 13 / 4; i += 128) dst[i] = src[i];
    }
    __syncthreads();

    u64 acc[26];
#pragma unroll
    for (int m = 0; m < 26; m++) acc[m] = bp[m];
#pragma unroll
    for (int d = 0; d < 13; d++) {
        const float xv = xs[tid * 13 + d];
        const u64 x2 = pk2(xv, xv);
        const ulonglong2* row = (const ulonglong2*)(wp + d * 26);
#pragma unroll
        for (int mm = 0; mm < 13; mm++) {
            const ulonglong2 w2 = row[mm];
            acc[2 * mm]     = fma2(w2.x, x2, acc[2 * mm]);
            acc[2 * mm + 1] = fma2(w2.y, x2, acc[2 * mm + 1]);
        }
    }
#pragma unroll
    for (int k = 0; k < 13; k++) {
        const float2 p01 = upk2(acc[k]);
        const float2 p23 = upk2(acc[13 + k]);
        *(float4*)(ot + tid * 56 + 4 * k) = make_float4(p01.x, p01.y, p23.x, p23.y);
    }
    __syncthreads();

    float4* preb = (float4*)(pre + ((size_t)seq * TLEN + t0) * G4);
    for (int j = tid; j < 128 * 13; j += 128) {
        const int r = j / 13, kk = j % 13;
        preb[j] = *(const float4*)(ot + r * 56 + kk * 4);
    }
}

// ---------------------------------------------------------------------------
// Pre kernel, layers 1-3 (D=26, reads compact y scratch [seq][t][13]).
// ---------------------------------------------------------------------------
__global__ void __launch_bounds__(128)
preR_kernel(const float* __restrict__ y,      // [NSEQ][TLEN][13]
            const float* __restrict__ w_ih,   // [2][52][26]
            const float* __restrict__ b_ih,
            const float* __restrict__ b_hh,
            float* __restrict__ pre)
{
    __shared__ alignas(16) u64 wp[26 * 26];
    __shared__ u64 bp[26];
    __shared__ alignas(16) float fb[128 * 13];
    __shared__ alignas(16) float bb[128 * 13];
    __shared__ alignas(16) float ot[128 * 56];

    const int tid = threadIdx.x;
    const int seq = blockIdx.x >> 5;
    const int t0  = (blockIdx.x & 31) * 128;
    const int dir = seq >> 7;
    const int b   = seq & 127;

    const float* W = w_ih + dir * G4 * 26;
    for (int idx = tid; idx < 26 * 26; idx += 128) {
        const int d = idx / 26, m = idx % 26;
        const int k = m % 13, s = m / 13;
        const int j0 = s ? 26 + k : k;
        const float s0 = s ? 1.0f : 0.5f;
        wp[idx] = pk2(s0 * W[j0 * 26 + d], 0.5f * W[(j0 + 13) * 26 + d]);
    }
    if (tid < 26) {
        const int k = tid % 13, s = tid / 13;
        const int j0 = s ? 26 + k : k;
        const float s0 = s ? 1.0f : 0.5f;
        const float* bi = b_ih + dir * G4;
        const float* bh = b_hh + dir * G4;
        bp[tid] = pk2(s0 * (bi[j0] + bh[j0]),
                      0.5f * (bi[j0 + 13] + bh[j0 + 13]));
    }
    {
        const float4* sf = (const float4*)(y + ((size_t)b * TLEN + t0) * 13);
        const float4* sb = (const float4*)(y + ((size_t)(BATCH + b) * TLEN + t0) * 13);
        float4* df = (float4*)fb;
        float4* db = (float4*)bb;
        for (int i = tid; i < 128 * 13 / 4; i += 128) { df[i] = sf[i]; db[i] = sb[i]; }
    }
    __syncthreads();

    u64 acc[26];
#pragma unroll
    for (int m = 0; m < 26; m++) acc[m] = bp[m];
#pragma unroll
    for (int d = 0; d < 26; d++) {
        const float xv = (d < 13) ? fb[tid * 13 + d] : bb[tid * 13 + (d - 13)];
        const u64 x2 = pk2(xv, xv);
        const ulonglong2* row = (const ulonglong2*)(wp + d * 26);
#pragma unroll
        for (int mm = 0; mm < 13; mm++) {
            const ulonglong2 w2 = row[mm];
            acc[2 * mm]     = fma2(w2.x, x2, acc[2 * mm]);
            acc[2 * mm + 1] = fma2(w2.y, x2, acc[2 * mm + 1]);
        }
    }
#pragma unroll
    for (int k = 0; k < 13; k++) {
        const float2 p01 = upk2(acc[k]);
        const float2 p23 = upk2(acc[13 + k]);
        *(float4*)(ot + tid * 56 + 4 * k) = make_float4(p01.x, p01.y, p23.x, p23.y);
    }
    __syncthreads();

    float4* preb = (float4*)(pre + ((size_t)seq * TLEN + t0) * G4);
    for (int j = tid; j < 128 * 13; j += 128) {
        const int r = j / 13, kk = j % 13;
        preb[j] = *(const float4*)(ot + r * 56 + kk * 4);
    }
}

// ---------------------------------------------------------------------------
// Recurrence: one warp per batch; lanes 0-12 fwd, 16-28 bwd. cp.async ring
// (depth 8, 16 slots). Activations all via MUFU.TANH; sigmoid pre-scale 0.5
// folded into weights/biases/pre-activations.
// ---------------------------------------------------------------------------
__global__ void __launch_bounds__(32)
lstm_rec_kernel(const float* __restrict__ pre,   // [NSEQ][TLEN][52]
                const float* __restrict__ w_hh,  // [2][52][13]
                float* __restrict__ yout)        // [NSEQ][TLEN][13]
{
    __shared__ alignas(16) float4 ring[16][32];

    const int lane = threadIdx.x;
    const int b    = blockIdx.x;
    const int dir  = lane >> 4;
    const int k    = lane & 15;
    const int kc   = (k < 13) ? k : 12;
    const bool act = (k < 13);

    const float* W = w_hh + dir * G4 * HID;
    u64 wA[13], wB[13];
#pragma unroll
    for (int kk = 0; kk < 13; kk++) {
        wA[kk] = pk2(0.5f * W[kc * HID + kk], 0.5f * W[(13 + kc) * HID + kk]);
        wB[kk] = pk2(W[(26 + kc) * HID + kk], 0.5f * W[(39 + kc) * HID + kk]);
    }

    const int seq = dir * BATCH + b;
    const int tstart = dir ? (TLEN - 1) : 0;
    const long long ss = (dir ? -1LL : 1LL) * (long long)(G4 * sizeof(float));

    const char* src0 = (const char*)(pre + ((size_t)seq * TLEN + tstart) * G4 + kc * 4);
    float* yp = yout + ((size_t)seq * TLEN + tstart) * HID + k;
    const long long ydel = (dir ? -1LL : 1LL) * HID;

    const unsigned sbase = (unsigned)__cvta_generic_to_shared(&ring[0][lane]);

#pragma unroll
    for (int u = 0; u < 8; u++) {
        cp16(sbase + u * (unsigned)sizeof(float4) * 32, src0 + (long long)u * ss);
        cp_commit();
    }
    const char* psrc = src0 + 8 * ss;

    float h = 0.0f, c = 0.0f;

    for (int blk = 0; blk < TLEN / 16; blk++) {
#pragma unroll
        for (int u = 0; u < 16; u++) {
            const int step = blk * 16 + u;
            if (step + 8 < TLEN)
                cp16(sbase + ((u + 8) & 15) * (unsigned)sizeof(float4) * 32, psrc);
            cp_commit();
            psrc += ss;
            cp_wait8();

            const float4 p = ring[u][lane];

            u64 a0 = 0ull, a1 = 0ull, c0 = 0ull, c1 = 0ull;
#pragma unroll
            for (int kk = 0; kk < 13; kk++) {
                const float hv = __shfl_sync(0xffffffffu, h, kk, 16);
                const u64 h2 = pk2(hv, hv);
                if (kk & 1) { c0 = fma2(wA[kk], h2, c0); c1 = fma2(wB[kk], h2, c1); }
                else        { a0 = fma2(wA[kk], h2, a0); a1 = fma2(wB[kk], h2, a1); }
            }
            a0 = add2(a0, add2(c0, pk2(p.x, p.y)));   // (0.5*i, 0.5*f)
            a1 = add2(a1, add2(c1, pk2(p.z, p.w)));   // (g, 0.5*o)

            const float2 g01 = upk2(a0);
            const float2 g23 = upk2(a1);
            const float tg = tanha(g23.x);
            const float si = fmaf(0.5f, tanha(g01.x), 0.5f);
            const float sf = fmaf(0.5f, tanha(g01.y), 0.5f);
            const float so = fmaf(0.5f, tanha(g23.y), 0.5f);

            c = fmaf(sf, c, si * tg);
            h = so * tanha(c);

            if (act) *yp = h;
            yp += ydel;
        }
    }
}

// ---------------------------------------------------------------------------
// Merge: y scratch [2][B][T][13] -> out [B][T][26]
// ---------------------------------------------------------------------------
__global__ void __launch_bounds__(128)
merge_kernel(const float* __restrict__ y, float* __restrict__ out)
{
    __shared__ alignas(16) float fb[128 * 13];
    __shared__ alignas(16) float bb[128 * 13];

    const int tid = threadIdx.x;
    const int b   = blockIdx.x >> 5;
    const int t0  = (blockIdx.x & 31) * 128;

    const float4* sf = (const float4*)(y + ((size_t)b * TLEN + t0) * 13);
    const float4* sb = (const float4*)(y + ((size_t)(BATCH + b) * TLEN + t0) * 13);
    float4* df = (float4*)fb;
    float4* db = (float4*)bb;
    for (int i = tid; i < 128 * 13 / 4; i += 128) { df[i] = sf[i]; db[i] = sb[i]; }
    __syncthreads();

    float4* ob = (float4*)(out + ((size_t)b * TLEN + t0) * 26);
    for (int j = tid; j < 128 * 26 / 4; j += 128) {
        float v[4];
#pragma unroll
        for (int e = 0; e < 4; e++) {
            const int f = j * 4 + e;
            const int t = f / 26, cidx = f % 26;
            v[e] = (cidx < 13) ? fb[t * 13 + cidx] : bb[t * 13 + (cidx - 13)];
        }
        ob[j] = make_float4(v[0], v[1], v[2], v[3]);
    }
}

// ---------------------------------------------------------------------------
// Launch
// ---------------------------------------------------------------------------
extern "C" void kernel_launch(void* const* d_in, const int* in_sizes, int n_in,
                              void* d_out, int out_size)
{
    const float* x      = (const float*)d_in[0];
    const float* w_ih0  = (const float*)d_in[1];
    const float* w_hh0  = (const float*)d_in[2];
    const float* b_ih0  = (const float*)d_in[3];
    const float* b_hh0  = (const float*)d_in[4];
    const float* w_ihr  = (const float*)d_in[5];
    const float* w_hhr  = (const float*)d_in[6];
    const float* b_ihr  = (const float*)d_in[7];
    const float* b_hhr  = (const float*)d_in[8];
    float* out = (float*)d_out;

    float *pre, *yA, *yB;
    cudaGetSymbolAddress((void**)&pre, g_pre);
    cudaGetSymbolAddress((void**)&yA,  g_yA);
    cudaGetSymbolAddress((void**)&yB,  g_yB);

    const int PRE_BLOCKS = NSEQ * (TLEN / 128);   // 8192

    // Layer 0
    pre0_kernel<<<PRE_BLOCKS, 128>>>(x, w_ih0, b_ih0, b_hh0, pre);
    lstm_rec_kernel<<<BATCH, 32>>>(pre, w_hh0, yA);

    // Layers 1-3
    const float* ins[3]  = {yA, yB, yA};
    float*       outs[3] = {yB, yA, yB};
    for (int l = 0; l < 3; l++) {
        preR_kernel<<<PRE_BLOCKS, 128>>>(ins[l],
                                         w_ihr + (size_t)l * 2 * G4 * 26,
                                         b_ihr + (size_t)l * 2 * G4,
                                         b_hhr + (size_t)l * 2 * G4,
                                         pre);
        lstm_rec_kernel<<<BATCH, 32>>>(pre,
                                       w_hhr + (size_t)l * 2 * G4 * HID,
                                       outs[l]);
    }

    // Final merge to [B][T][26]
    merge_kernel<<<BATCH * (TLEN / 128), 128>>>(yB, out);
}